// round 16
// baseline (speedup 1.0000x reference)
#include <cuda_runtime.h>
#include <cuda_bf16.h>
#include <math.h>
#include <stdint.h>

#define NTHREADS 640
#define NWARPS   (NTHREADS/32)
#define NENS 8
#define HID 64

#define TANH_C  2.8853900817779268f   // 2*log2(e) folded into W1,b1,W2,b2
#define LOG2E   1.4426950408889634f   // folded into W3,b3
#define LN2     0.6931471805599453f

// packed weight records in __device__ scratch (allocation-free)
__device__ __align__(16) uint4  g_w2p[NENS * 8 * 4 * 32];   // 131072 B
__device__ __align__(16) uint4  g_w1p[NENS * 8 * 32];       // 32768 B
__device__ __align__(16) float4 g_bw [NENS * 8 * 4];        // 4096 B
__device__ float g_b3s[NENS];

// ---- shared memory byte offsets ----
#define SM_W2P 0
#define SM_W1P (SM_W2P + 131072)
#define SM_BW  (SM_W1P + 32768)            // 163840
#define SM_B3  (SM_BW + 4096)              // 167936
#define SM_X   (SM_B3 + 32)                // 167968
#define SM_ZP  (SM_X + NWARPS*16*8*4)      // 178208: [wid][e(8)+side*8][lane] f32
#define SMEM_BYTES (SM_ZP + NWARPS*512*4)  // 219168

// ---- MUFU approx primitives ----
__device__ __forceinline__ float fast_rcp(float x) {
    float r; asm("rcp.approx.f32 %0, %1;" : "=f"(r) : "f"(x)); return r;
}
__device__ __forceinline__ float fast_rsqrt(float x) {
    float r; asm("rsqrt.approx.f32 %0, %1;" : "=f"(r) : "f"(x)); return r;
}
__device__ __forceinline__ float fast_sqrt(float x) {
    float r; asm("sqrt.approx.f32 %0, %1;" : "=f"(r) : "f"(x)); return r;
}
__device__ __forceinline__ float fast_log(float x) {
    float l; asm("lg2.approx.f32 %0, %1;" : "=f"(l) : "f"(x)); return l * LN2;
}
__device__ __forceinline__ float fast_ex2(float s) {
    float e; asm("ex2.approx.f32 %0, %1;" : "=f"(e) : "f"(s)); return e;
}

// Quad-batched r_i = 1/(ex2(s_i)+1), one rcp for four values (layer 1 only;
// layer 2 uses the factored-z form inline).
__device__ __forceinline__ void quad_r(float s0, float s1, float s2, float s3,
                                       float& r0, float& r1, float& r2, float& r3)
{
    float e0p = fast_ex2(s0) + 1.0f;
    float e1p = fast_ex2(s1) + 1.0f;
    float e2p = fast_ex2(s2) + 1.0f;
    float e3p = fast_ex2(s3) + 1.0f;
    float pa = e0p * e1p, pb = e2p * e3p;
    float q  = fast_rcp(pa * pb);
    float qa = q * pb, qb = q * pa;
    r0 = qa * e1p;  r1 = qa * e0p;
    r2 = qb * e3p;  r3 = qb * e2p;
}

// ---- bf16x2 pack + hi/lo split ----
__device__ __forceinline__ void split2(float v0, float v1, uint32_t& hi, uint32_t& lo) {
    __nv_bfloat162 h = __floats2bfloat162_rn(v0, v1);
    hi = *reinterpret_cast<uint32_t*>(&h);
    float f0 = __uint_as_float(hi << 16);
    float f1 = __uint_as_float(hi & 0xffff0000u);
    __nv_bfloat162 l = __floats2bfloat162_rn(v0 - f0, v1 - f1);
    lo = *reinterpret_cast<uint32_t*>(&l);
}

// ---- mma.sync m16n8k16 / m16n8k8, bf16, fp32 accum ----
__device__ __forceinline__ void mma16816(float& c0, float& c1, float& c2, float& c3,
    uint32_t a0, uint32_t a1, uint32_t a2, uint32_t a3, uint32_t b0, uint32_t b1)
{
    asm volatile("mma.sync.aligned.m16n8k16.row.col.f32.bf16.bf16.f32 "
        "{%0,%1,%2,%3},{%4,%5,%6,%7},{%8,%9},{%0,%1,%2,%3};"
        : "+f"(c0), "+f"(c1), "+f"(c2), "+f"(c3)
        : "r"(a0), "r"(a1), "r"(a2), "r"(a3), "r"(b0), "r"(b1));
}
__device__ __forceinline__ void mma16808(float& c0, float& c1, float& c2, float& c3,
    uint32_t a0, uint32_t a1, uint32_t b0)
{
    asm volatile("mma.sync.aligned.m16n8k8.row.col.f32.bf16.bf16.f32 "
        "{%0,%1,%2,%3},{%4,%5},{%6},{%0,%1,%2,%3};"
        : "+f"(c0), "+f"(c1), "+f"(c2), "+f"(c3)
        : "r"(a0), "r"(a1), "r"(b0));
}

// Light vstar-only shock (invariants hoisted). 9 MUFU.
__device__ __forceinline__ float vstar_light(float pC, float p, float v, float sgn,
    float rrho, float omv2, float h, float hW, float a2, float irW)
{
    float dp   = p - pC;
    float rpC  = fast_rcp(pC);
    float t04  = 0.4f * dp * rpC;
    float A    = 1.0f + t04;
    float C    = h * dp * rrho - h * h;
    float disc = fmaxf(fmaf(t04, t04, -4.0f * A * C), 0.0f);
    float hC   = (fast_sqrt(disc) + t04) * (0.5f * fast_rcp(A));
    float hCm1 = hC - 1.0f;
    float denj = h * rrho - 0.4f * hC * hCm1 * rpC;
    float j2   = fmaxf((pC - p) * fast_rcp(denj), 1e-12f);
    float rj   = fast_rsqrt(j2);
    float jabs = j2 * rj;
    float Vs   = (a2 * v + sgn * jabs * fast_sqrt(fmaf(a2, omv2, j2))) * fast_rcp(a2 + j2);
    float Ws   = fast_rsqrt(fmaxf(1.0f - Vs * Vs, 1e-12f));
    float rjs  = sgn * rj;
    float num  = hW * v + Ws * (pC - p) * rjs;
    float den  = hW + (pC - p) * (Ws * v * rjs + irW);
    return num * fast_rcp(den);
}

// Full shock (final recompute only).
__device__ __forceinline__ void get_vel_shock(
    float pC, float rho, float p, float v, float sign,
    float& rhoC, float& hC, float& vstar, float& Vs)
{
    float rrho = fast_rcp(rho);
    float h    = fmaf(2.5f * p, rrho, 1.0f);
    float omv2 = 1.0f - v * v;
    float W    = fast_rsqrt(omv2);
    float dp   = p - pC;
    float rpC  = fast_rcp(pC);
    float t04  = 0.4f * dp * rpC;
    float A    = 1.0f + t04;
    float B    = -t04;
    float C    = h * dp * rrho - h * h;
    float disc = fmaxf(fmaf(B, B, -4.0f * A * C), 0.0f);
    hC   = (fast_sqrt(disc) - B) * (0.5f * fast_rcp(A));
    float hCm1 = hC - 1.0f;
    rhoC = 2.5f * pC * fast_rcp(hCm1);
    float denj = h * rrho - 0.4f * hC * hCm1 * rpC;
    float j2   = fmaxf((pC - p) * fast_rcp(denj), 1e-12f);
    float jabs = fast_sqrt(j2);
    float rw   = rho * W;
    float a2   = rw * rw;
    Vs = (a2 * v + sign * jabs * fast_sqrt(fmaf(a2, omv2, j2))) * fast_rcp(a2 + j2);
    float Ws = fast_rsqrt(fmaxf(1.0f - Vs * Vs, 1e-12f));
    float js = sign * jabs;
    float rjs = fast_rcp(js);
    float hW  = h * W;
    float num = hW * v + Ws * (pC - p) * rjs;
    float den = hW + (pC - p) * (Ws * v * rjs + rrho * omv2 * W);
    vstar = num * fast_rcp(den);
}

// ---- prep: build packed fragment tables (all scales + affine folds) ----
__global__ void prep_kernel(const float* __restrict__ W1, const float* __restrict__ W2,
                            const float* __restrict__ b1, const float* __restrict__ b2,
                            const float* __restrict__ W3, const float* __restrict__ b3)
{
    const int nW2 = NENS*8*4*32, nW1 = NENS*8*32, nBW = NENS*8*4;
    int idx = blockIdx.x * blockDim.x + threadIdx.x;
    if (idx < nW2) {                               // B-frags of (-2*TANH_C*W2)
        int lane = idx & 31, kt = (idx >> 5) & 3, nt = (idx >> 7) & 7, e = idx >> 10;
        int gg = lane >> 2, t = lane & 3;
        int n = nt * 8 + gg;
        int kb = kt * 16 + 2 * t;
        const float s = -2.0f * TANH_C;
        float w00 = s * W2[(e*HID + kb    )*HID + n], w01 = s * W2[(e*HID + kb + 1)*HID + n];
        float w10 = s * W2[(e*HID + kb + 8)*HID + n], w11 = s * W2[(e*HID + kb + 9)*HID + n];
        uint32_t h0, l0, h1, l1;
        split2(w00, w01, h0, l0);
        split2(w10, w11, h1, l1);
        g_w2p[idx] = make_uint4(h0, h1, l0, l1);
    } else if (idx < nW2 + nW1) {                  // W1 packed + bias (TANH_C-scaled)
        int j = idx - nW2;
        int lane = j & 31, nt = (j >> 5) & 7, e = j >> 8;
        int gg = lane >> 2, t = lane & 3;
        int n = nt * 8 + gg;
        int k = 2 * t;
        float w0 = (k     < 6) ? TANH_C * W1[(e*6 + k    )*HID + n] : 0.0f;
        float w1 = (k + 1 < 6) ? TANH_C * W1[(e*6 + k + 1)*HID + n] : 0.0f;
        uint32_t h0, l0;
        split2(w0, w1, h0, l0);
        float bias0 = TANH_C * b1[e*HID + nt*8 + 2*t];
        float bias1 = TANH_C * b1[e*HID + nt*8 + 2*t + 1];
        g_w1p[j] = make_uint4(h0, l0, __float_as_uint(bias0), __float_as_uint(bias1));
    } else if (idx < nW2 + nW1 + nBW) {            // b2' = TANH_C*(b2 + colsum W2); w3' = -2*log2e*w3
        int j = idx - nW2 - nW1;
        int t = j & 3, nt = (j >> 2) & 7, e = j >> 5;
        int base = e*HID + nt*8 + 2*t;
        float cs0 = b2[base], cs1 = b2[base + 1];
        for (int k = 0; k < HID; k++) {
            cs0 += W2[(e*HID + k)*HID + (nt*8 + 2*t)];
            cs1 += W2[(e*HID + k)*HID + (nt*8 + 2*t + 1)];
        }
        g_bw[j] = make_float4(TANH_C * cs0, TANH_C * cs1,
                              -2.0f * LOG2E * W3[base], -2.0f * LOG2E * W3[base+1]);
    } else if (idx < nW2 + nW1 + nBW + NENS) {     // b3' = log2e*(b3 + sum w3)
        int e = idx - nW2 - nW1 - nBW;
        float s = b3[e];
        for (int j = 0; j < HID; j++) s += W3[e*HID + j];
        g_b3s[e] = LOG2E * s;
    }
}

__global__ void __launch_bounds__(NTHREADS, 1)
solver_mma(const float* __restrict__ P, const float* __restrict__ F,
           float* __restrict__ out, int N)
{
    extern __shared__ char smem[];
    uint4*  sW2p = (uint4*)(smem + SM_W2P);
    uint4*  sW1p = (uint4*)(smem + SM_W1P);
    float4* sBW  = (float4*)(smem + SM_BW);
    float*  sB3  = (float*)(smem + SM_B3);
    float*  sX   = (float*)(smem + SM_X);

    // cooperative smem fill
    {
        const int4* s1 = (const int4*)g_w2p;  int4* d1 = (int4*)sW2p;
        for (int i = threadIdx.x; i < NENS*8*4*32; i += NTHREADS) d1[i] = s1[i];
        const int4* s2 = (const int4*)g_w1p;  int4* d2 = (int4*)sW1p;
        for (int i = threadIdx.x; i < NENS*8*32; i += NTHREADS) d2[i] = s2[i];
        const int4* s3 = (const int4*)g_bw;   int4* d3 = (int4*)sBW;
        for (int i = threadIdx.x; i < NENS*8*4; i += NTHREADS) d3[i] = s3[i];
        if (threadIdx.x < NENS) sB3[threadIdx.x] = g_b3s[threadIdx.x];
    }
    __syncthreads();

    const int lane = threadIdx.x & 31, wid = threadIdx.x >> 5;
    const int g = lane >> 2, t = lane & 3;
    const int side = lane >> 4;          // 0 = Left state, 1 = Right state
    const int c    = lane & 15;          // cell index within tile
    const float sgn = side ? 1.0f : -1.0f;
    const int ntiles = (N + 15) >> 4;
    float* Xw  = sX + wid * 128;
    float* ZPw = (float*)(smem + SM_ZP) + wid * 512;   // [e + side8*8][lane]

    for (int tile = blockIdx.x * NWARPS + wid; tile < ntiles; tile += gridDim.x * NWARPS) {
        const int cell = tile * 16 + c;
        const bool act = (cell < N);

        // each lane owns ONE side of one cell; prefetch flux early
        float rho = 1.0f, p = 1.0f, v = 0.0f;
        float fx0 = 0.0f, fx1 = 0.0f, fx2 = 0.0f;
        if (act) {
            rho = P[cell*6 + side];
            p   = P[cell*6 + 2 + side];
            v   = P[cell*6 + 4 + side];
            fx0 = F[cell*6 + side];
            fx1 = F[cell*6 + 2 + side];
            fx2 = F[cell*6 + 4 + side];
            Xw[c*8 + side]     = fast_log(rho);
            Xw[c*8 + 2 + side] = fast_log(p);
            Xw[c*8 + 4 + side] = v;
        } else {
            Xw[c*8 + side]     = 0.0f;
            Xw[c*8 + 2 + side] = 0.0f;
            Xw[c*8 + 4 + side] = 0.0f;
        }
        if (side == 0) { Xw[c*8 + 6] = 0.0f; Xw[c*8 + 7] = 0.0f; }
        __syncwarp();
        const float aPress = fmaxf(p, __shfl_xor_sync(0xffffffffu, p, 16));

        // per-lane shock invariants
        const float rrho = fast_rcp(rho);
        const float omv2 = 1.0f - v * v;
        const float Wl   = fast_rsqrt(omv2);
        const float hh   = fmaf(2.5f * p, rrho, 1.0f);
        const float hW   = hh * Wl;
        const float rw   = rho * Wl;
        const float a2   = rw * rw;
        const float irW  = rrho * omv2 * Wl;

        // layer1 A-fragments
        uint32_t a1h0, a1l0, a1h1, a1l1;
        {
            float2 f  = *(float2*)&Xw[g*8 + 2*t];
            float2 f8 = *(float2*)&Xw[(g+8)*8 + 2*t];
            split2(f.x,  f.y,  a1h0, a1l0);
            split2(f8.x, f8.y, a1h1, a1l1);
        }
        __syncwarp();

        for (int e = 0; e < NENS; e++) {
            // ---- layer 1: X[16x8] @ W1[8x64] via m16n8k8 ----
            uint32_t A2h[4][4], A2l[4][4];
            const uint4* w1p = sW1p + (e * 8) * 32 + lane;
            #pragma unroll
            for (int nt = 0; nt < 8; nt++) {
                uint4 w = w1p[nt * 32];
                float cH0 = __uint_as_float(w.z), cH1 = __uint_as_float(w.w);
                float cH2 = cH0, cH3 = cH1;
                float cM0=0,cM1=0,cM2=0,cM3=0;
                mma16808(cH0,cH1,cH2,cH3, a1h0,a1h1, w.x);
                mma16808(cM0,cM1,cM2,cM3, a1h0,a1h1, w.y);
                mma16808(cM0,cM1,cM2,cM3, a1l0,a1l1, w.x);
                float r0, r1, r2, r3;
                quad_r(cH0+cM0, cH1+cM1, cH2+cM2, cH3+cM3, r0, r1, r2, r3);
                int kt = nt >> 1, hhp = (nt & 1) * 2;
                split2(r0, r1, A2h[kt][hhp],     A2l[kt][hhp]);
                split2(r2, r3, A2h[kt][hhp + 1], A2l[kt][hhp + 1]);
            }

            // ---- layers 2+3: 2 accumulator chains + factored z-recovery ----
            float zp0 = 0.0f, zp1 = 0.0f;
            const uint4* w2p = sW2p + (e * 8) * 4 * 32 + lane;
            #pragma unroll 2
            for (int nt = 0; nt < 8; nt++) {
                float4 bw = sBW[(e*8 + nt)*4 + t];
                float cH0=bw.x, cH1=bw.y, cH2=bw.x, cH3=bw.y;
                float cM0=0,cM1=0,cM2=0,cM3=0;
                const uint4* wrow = w2p + nt * (4*32);
                #pragma unroll
                for (int kt = 0; kt < 4; kt++) {
                    uint4 w = wrow[kt * 32];
                    mma16816(cH0,cH1,cH2,cH3, A2h[kt][0],A2h[kt][1],A2h[kt][2],A2h[kt][3], w.x,w.y);
                    mma16816(cM0,cM1,cM2,cM3, A2h[kt][0],A2h[kt][1],A2h[kt][2],A2h[kt][3], w.z,w.w);
                    mma16816(cM0,cM1,cM2,cM3, A2l[kt][0],A2l[kt][1],A2l[kt][2],A2l[kt][3], w.x,w.y);
                }
                // factored z: zp0 += q*pb*(w3z*e1p + w3w*e0p); zp1 += q*pa*(...)
                float e0p = fast_ex2(cH0 + cM0) + 1.0f;
                float e1p = fast_ex2(cH1 + cM1) + 1.0f;
                float e2p = fast_ex2(cH2 + cM2) + 1.0f;
                float e3p = fast_ex2(cH3 + cM3) + 1.0f;
                float pa = e0p * e1p, pb = e2p * e3p;
                float q  = fast_rcp(pa * pb);
                float u0 = bw.z * e1p;  u0 = fmaf(bw.w, e0p, u0);
                float u1 = bw.z * e3p;  u1 = fmaf(bw.w, e2p, u1);
                float qb_ = q * pb, qa_ = q * pa;
                zp0 = fmaf(u0, qb_, zp0);
                zp1 = fmaf(u1, qa_, zp1);
            }
            // stash partials; ALL reductions + shocks deferred past the loop
            ZPw[e*32 + lane]       = zp0;
            ZPw[256 + e*32 + lane] = zp1;
        }
        __syncwarp();

        // ============ deferred tail: 8 reductions + 8 shocks, full ILP =====
        float zA[NENS], zB[NENS];
        #pragma unroll
        for (int e = 0; e < NENS; e++) {
            zA[e] = ZPw[e*32 + lane];
            zB[e] = ZPw[256 + e*32 + lane];
        }
        #pragma unroll
        for (int e = 0; e < NENS; e++) {
            zA[e] += __shfl_xor_sync(0xffffffffu, zA[e], 1);
            zB[e] += __shfl_xor_sync(0xffffffffu, zB[e], 1);
        }
        #pragma unroll
        for (int e = 0; e < NENS; e++) {
            zA[e] += __shfl_xor_sync(0xffffffffu, zA[e], 2);
            zB[e] += __shfl_xor_sync(0xffffffffu, zB[e], 2);
        }
        const int src = (c & 7) * 4;
        float pc[NENS];
        #pragma unroll
        for (int e = 0; e < NENS; e++) {
            float za = __shfl_sync(0xffffffffu, zA[e], src);
            float zb = __shfl_sync(0xffffffffu, zB[e], src);
            float z  = ((c < 8) ? za : zb) + sB3[e];   // log2e-scaled
            pc[e] = aPress * fmaf(2.0f, fast_ex2(z), 1.0f);
        }
        float vs[NENS];
        #pragma unroll
        for (int e = 0; e < NENS; e++)
            vs[e] = vstar_light(pc[e], p, v, sgn, rrho, omv2, hh, hW, a2, irW);

        float bestdiff = 3.4e38f, bestP = 0.0f;
        #pragma unroll
        for (int e = 0; e < NENS; e++) {
            float vsO = __shfl_xor_sync(0xffffffffu, vs[e], 16);
            float d = fabsf(vs[e] - vsO);     // symmetric: both lanes agree
            if (d < bestdiff) { bestdiff = d; bestP = pc[e]; }
        }

        // final shock recompute, parallel over sides; exchange via shfl
        float rhoC, hC, vstar, vsh;
        get_vel_shock(bestP, rho, p, v, sgn, rhoC, hC, vstar, vsh);
        float vstarO = __shfl_xor_sync(0xffffffffu, vstar, 16);
        float vshO   = __shfl_xor_sync(0xffffffffu, vsh,   16);
        float rhoCO  = __shfl_xor_sync(0xffffffffu, rhoC,  16);
        float hCO    = __shfl_xor_sync(0xffffffffu, hC,    16);
        float fR0    = __shfl_xor_sync(0xffffffffu, fx0,   16);
        float fR1    = __shfl_xor_sync(0xffffffffu, fx1,   16);
        float fR2    = __shfl_xor_sync(0xffffffffu, fx2,   16);

        if (side == 0 && act) {
            float lam = 0.5f * (vstarO + vstar);
            float WC  = fast_rsqrt(1.0f - lam * lam);
            float densCL = WC * rhoC, densCR = WC * rhoCO;

            float f0 = 0.0f, f1 = 0.0f, f2 = 0.0f;
            if (vsh >= 0.0f) { f0 = fx0; f1 = fx1; f2 = fx2; }
            if (vsh < 0.0f && lam > 0.0f) {
                f0 = densCL * lam;
                f1 = densCL * (WC * hC - 1.0f) * lam;
                f2 = (WC * WC * rhoC * hC * lam) * lam + bestP;
            }
            if (lam <= 0.0f && vshO > 0.0f) {
                f0 = densCR * lam;
                f1 = densCR * (WC * hCO - 1.0f) * lam;
                f2 = (WC * WC * rhoCO * hCO * lam) * lam + bestP;
            }
            if (vshO <= 0.0f) { f0 = fR0; f1 = fR1; f2 = fR2; }
            out[cell*3+0] = f0; out[cell*3+1] = f1; out[cell*3+2] = f2;
        }
    }
}

extern "C" void kernel_launch(void* const* d_in, const int* in_sizes, int n_in,
                              void* d_out, int out_size)
{
    const float* P  = (const float*)d_in[0];
    const float* F  = (const float*)d_in[2];
    const float* W1 = (const float*)d_in[5];
    const float* b1 = (const float*)d_in[6];
    const float* W2 = (const float*)d_in[7];
    const float* b2 = (const float*)d_in[8];
    const float* W3 = (const float*)d_in[9];
    const float* b3 = (const float*)d_in[10];
    float* out = (float*)d_out;
    const int N = in_sizes[0] / 6;

    const int nprep = NENS*8*4*32 + NENS*8*32 + NENS*8*4 + NENS;
    prep_kernel<<<(nprep + 255) / 256, 256>>>(W1, W2, b1, b2, W3, b3);

    cudaFuncSetAttribute(solver_mma,
                         cudaFuncAttributeMaxDynamicSharedMemorySize, SMEM_BYTES);
    solver_mma<<<148, NTHREADS, SMEM_BYTES>>>(P, F, out, N);
}

// round 17
// speedup vs baseline: 1.5402x; 1.5402x over previous
#include <cuda_runtime.h>
#include <cuda_bf16.h>
#include <math.h>
#include <stdint.h>

#define NTHREADS 640
#define NWARPS   (NTHREADS/32)
#define NENS 8
#define HID 64

#define TANH_C  2.8853900817779268f   // 2*log2(e) folded into W1,b1,W2,b2
#define LOG2E   1.4426950408889634f   // folded into W3,b3
#define LN2     0.6931471805599453f

// packed weight records in __device__ scratch (allocation-free)
__device__ __align__(16) uint4  g_w2p[NENS * 8 * 4 * 32];   // 131072 B
__device__ __align__(16) uint4  g_w1p[NENS * 8 * 32];       // 32768 B
__device__ __align__(16) float4 g_bw [NENS * 8 * 4];        // 4096 B
__device__ float g_b3s[NENS];

// ---- shared memory byte offsets ----
#define SM_W2P 0
#define SM_W1P (SM_W2P + 131072)
#define SM_BW  (SM_W1P + 32768)            // 163840
#define SM_B3  (SM_BW + 4096)              // 167936
#define SM_X   (SM_B3 + 32)                // 167968
#define SM_ZP  (SM_X + NWARPS*16*8*4)      // 178208: [wid][e(8)+side*8][lane] f32
#define SMEM_BYTES (SM_ZP + NWARPS*512*4)  // 219168

// ---- MUFU approx primitives ----
__device__ __forceinline__ float fast_rcp(float x) {
    float r; asm("rcp.approx.f32 %0, %1;" : "=f"(r) : "f"(x)); return r;
}
__device__ __forceinline__ float fast_rsqrt(float x) {
    float r; asm("rsqrt.approx.f32 %0, %1;" : "=f"(r) : "f"(x)); return r;
}
__device__ __forceinline__ float fast_sqrt(float x) {
    float r; asm("sqrt.approx.f32 %0, %1;" : "=f"(r) : "f"(x)); return r;
}
__device__ __forceinline__ float fast_log(float x) {
    float l; asm("lg2.approx.f32 %0, %1;" : "=f"(l) : "f"(x)); return l * LN2;
}
__device__ __forceinline__ float fast_ex2(float s) {
    float e; asm("ex2.approx.f32 %0, %1;" : "=f"(e) : "f"(s)); return e;
}

// Quad-batched r_i = 1/(ex2(s_i)+1), one rcp for four values (layer 1).
__device__ __forceinline__ void quad_r(float s0, float s1, float s2, float s3,
                                       float& r0, float& r1, float& r2, float& r3)
{
    float e0p = fast_ex2(s0) + 1.0f;
    float e1p = fast_ex2(s1) + 1.0f;
    float e2p = fast_ex2(s2) + 1.0f;
    float e3p = fast_ex2(s3) + 1.0f;
    float pa = e0p * e1p, pb = e2p * e3p;
    float q  = fast_rcp(pa * pb);
    float qa = q * pb, qb = q * pa;
    r0 = qa * e1p;  r1 = qa * e0p;
    r2 = qb * e3p;  r3 = qb * e2p;
}

// ---- bf16x2 pack + hi/lo split ----
__device__ __forceinline__ void split2(float v0, float v1, uint32_t& hi, uint32_t& lo) {
    __nv_bfloat162 h = __floats2bfloat162_rn(v0, v1);
    hi = *reinterpret_cast<uint32_t*>(&h);
    float f0 = __uint_as_float(hi << 16);
    float f1 = __uint_as_float(hi & 0xffff0000u);
    __nv_bfloat162 l = __floats2bfloat162_rn(v0 - f0, v1 - f1);
    lo = *reinterpret_cast<uint32_t*>(&l);
}

// ---- mma.sync m16n8k16 / m16n8k8, bf16, fp32 accum ----
__device__ __forceinline__ void mma16816(float& c0, float& c1, float& c2, float& c3,
    uint32_t a0, uint32_t a1, uint32_t a2, uint32_t a3, uint32_t b0, uint32_t b1)
{
    asm volatile("mma.sync.aligned.m16n8k16.row.col.f32.bf16.bf16.f32 "
        "{%0,%1,%2,%3},{%4,%5,%6,%7},{%8,%9},{%0,%1,%2,%3};"
        : "+f"(c0), "+f"(c1), "+f"(c2), "+f"(c3)
        : "r"(a0), "r"(a1), "r"(a2), "r"(a3), "r"(b0), "r"(b1));
}
__device__ __forceinline__ void mma16808(float& c0, float& c1, float& c2, float& c3,
    uint32_t a0, uint32_t a1, uint32_t b0)
{
    asm volatile("mma.sync.aligned.m16n8k8.row.col.f32.bf16.bf16.f32 "
        "{%0,%1,%2,%3},{%4,%5},{%6},{%0,%1,%2,%3};"
        : "+f"(c0), "+f"(c1), "+f"(c2), "+f"(c3)
        : "r"(a0), "r"(a1), "r"(b0));
}

// Light vstar-only shock (invariants hoisted). 9 MUFU.
__device__ __forceinline__ float vstar_light(float pC, float p, float v, float sgn,
    float rrho, float omv2, float h, float hW, float a2, float irW)
{
    float dp   = p - pC;
    float rpC  = fast_rcp(pC);
    float t04  = 0.4f * dp * rpC;
    float A    = 1.0f + t04;
    float C    = h * dp * rrho - h * h;
    float disc = fmaxf(fmaf(t04, t04, -4.0f * A * C), 0.0f);
    float hC   = (fast_sqrt(disc) + t04) * (0.5f * fast_rcp(A));
    float hCm1 = hC - 1.0f;
    float denj = h * rrho - 0.4f * hC * hCm1 * rpC;
    float j2   = fmaxf((pC - p) * fast_rcp(denj), 1e-12f);
    float rj   = fast_rsqrt(j2);
    float jabs = j2 * rj;
    float Vs   = (a2 * v + sgn * jabs * fast_sqrt(fmaf(a2, omv2, j2))) * fast_rcp(a2 + j2);
    float Ws   = fast_rsqrt(fmaxf(1.0f - Vs * Vs, 1e-12f));
    float rjs  = sgn * rj;
    float num  = hW * v + Ws * (pC - p) * rjs;
    float den  = hW + (pC - p) * (Ws * v * rjs + irW);
    return num * fast_rcp(den);
}

// Full shock (final recompute only).
__device__ __forceinline__ void get_vel_shock(
    float pC, float rho, float p, float v, float sign,
    float& rhoC, float& hC, float& vstar, float& Vs)
{
    float rrho = fast_rcp(rho);
    float h    = fmaf(2.5f * p, rrho, 1.0f);
    float omv2 = 1.0f - v * v;
    float W    = fast_rsqrt(omv2);
    float dp   = p - pC;
    float rpC  = fast_rcp(pC);
    float t04  = 0.4f * dp * rpC;
    float A    = 1.0f + t04;
    float B    = -t04;
    float C    = h * dp * rrho - h * h;
    float disc = fmaxf(fmaf(B, B, -4.0f * A * C), 0.0f);
    hC   = (fast_sqrt(disc) - B) * (0.5f * fast_rcp(A));
    float hCm1 = hC - 1.0f;
    rhoC = 2.5f * pC * fast_rcp(hCm1);
    float denj = h * rrho - 0.4f * hC * hCm1 * rpC;
    float j2   = fmaxf((pC - p) * fast_rcp(denj), 1e-12f);
    float jabs = fast_sqrt(j2);
    float rw   = rho * W;
    float a2   = rw * rw;
    Vs = (a2 * v + sign * jabs * fast_sqrt(fmaf(a2, omv2, j2))) * fast_rcp(a2 + j2);
    float Ws = fast_rsqrt(fmaxf(1.0f - Vs * Vs, 1e-12f));
    float js = sign * jabs;
    float rjs = fast_rcp(js);
    float hW  = h * W;
    float num = hW * v + Ws * (pC - p) * rjs;
    float den = hW + (pC - p) * (Ws * v * rjs + rrho * omv2 * W);
    vstar = num * fast_rcp(den);
}

// ---- prep: build packed fragment tables (all scales + affine folds) ----
__global__ void prep_kernel(const float* __restrict__ W1, const float* __restrict__ W2,
                            const float* __restrict__ b1, const float* __restrict__ b2,
                            const float* __restrict__ W3, const float* __restrict__ b3)
{
    const int nW2 = NENS*8*4*32, nW1 = NENS*8*32, nBW = NENS*8*4;
    int idx = blockIdx.x * blockDim.x + threadIdx.x;
    if (idx < nW2) {                               // B-frags of (-2*TANH_C*W2)
        int lane = idx & 31, kt = (idx >> 5) & 3, nt = (idx >> 7) & 7, e = idx >> 10;
        int gg = lane >> 2, t = lane & 3;
        int n = nt * 8 + gg;
        int kb = kt * 16 + 2 * t;
        const float s = -2.0f * TANH_C;
        float w00 = s * W2[(e*HID + kb    )*HID + n], w01 = s * W2[(e*HID + kb + 1)*HID + n];
        float w10 = s * W2[(e*HID + kb + 8)*HID + n], w11 = s * W2[(e*HID + kb + 9)*HID + n];
        uint32_t h0, l0, h1, l1;
        split2(w00, w01, h0, l0);
        split2(w10, w11, h1, l1);
        g_w2p[idx] = make_uint4(h0, h1, l0, l1);
    } else if (idx < nW2 + nW1) {                  // W1 packed + bias (TANH_C-scaled)
        int j = idx - nW2;
        int lane = j & 31, nt = (j >> 5) & 7, e = j >> 8;
        int gg = lane >> 2, t = lane & 3;
        int n = nt * 8 + gg;
        int k = 2 * t;
        float w0 = (k     < 6) ? TANH_C * W1[(e*6 + k    )*HID + n] : 0.0f;
        float w1 = (k + 1 < 6) ? TANH_C * W1[(e*6 + k + 1)*HID + n] : 0.0f;
        uint32_t h0, l0;
        split2(w0, w1, h0, l0);
        float bias0 = TANH_C * b1[e*HID + nt*8 + 2*t];
        float bias1 = TANH_C * b1[e*HID + nt*8 + 2*t + 1];
        g_w1p[j] = make_uint4(h0, l0, __float_as_uint(bias0), __float_as_uint(bias1));
    } else if (idx < nW2 + nW1 + nBW) {            // b2' = TANH_C*(b2 + colsum W2); w3' = -2*log2e*w3
        int j = idx - nW2 - nW1;
        int t = j & 3, nt = (j >> 2) & 7, e = j >> 5;
        int base = e*HID + nt*8 + 2*t;
        float cs0 = b2[base], cs1 = b2[base + 1];
        for (int k = 0; k < HID; k++) {
            cs0 += W2[(e*HID + k)*HID + (nt*8 + 2*t)];
            cs1 += W2[(e*HID + k)*HID + (nt*8 + 2*t + 1)];
        }
        g_bw[j] = make_float4(TANH_C * cs0, TANH_C * cs1,
                              -2.0f * LOG2E * W3[base], -2.0f * LOG2E * W3[base+1]);
    } else if (idx < nW2 + nW1 + nBW + NENS) {     // b3' = log2e*(b3 + sum w3)
        int e = idx - nW2 - nW1 - nBW;
        float s = b3[e];
        for (int j = 0; j < HID; j++) s += W3[e*HID + j];
        g_b3s[e] = LOG2E * s;
    }
}

__global__ void __launch_bounds__(NTHREADS, 1)
solver_mma(const float* __restrict__ P, const float* __restrict__ F,
           float* __restrict__ out, int N)
{
    extern __shared__ char smem[];
    uint4*  sW2p = (uint4*)(smem + SM_W2P);
    uint4*  sW1p = (uint4*)(smem + SM_W1P);
    float4* sBW  = (float4*)(smem + SM_BW);
    float*  sB3  = (float*)(smem + SM_B3);
    float*  sX   = (float*)(smem + SM_X);

    // cooperative smem fill
    {
        const int4* s1 = (const int4*)g_w2p;  int4* d1 = (int4*)sW2p;
        for (int i = threadIdx.x; i < NENS*8*4*32; i += NTHREADS) d1[i] = s1[i];
        const int4* s2 = (const int4*)g_w1p;  int4* d2 = (int4*)sW1p;
        for (int i = threadIdx.x; i < NENS*8*32; i += NTHREADS) d2[i] = s2[i];
        const int4* s3 = (const int4*)g_bw;   int4* d3 = (int4*)sBW;
        for (int i = threadIdx.x; i < NENS*8*4; i += NTHREADS) d3[i] = s3[i];
        if (threadIdx.x < NENS) sB3[threadIdx.x] = g_b3s[threadIdx.x];
    }
    __syncthreads();

    const int lane = threadIdx.x & 31, wid = threadIdx.x >> 5;
    const int g = lane >> 2, t = lane & 3;
    const int side = lane >> 4;          // 0 = Left state, 1 = Right state
    const int c    = lane & 15;          // cell index within tile
    const float sgn = side ? 1.0f : -1.0f;
    const int ntiles = (N + 15) >> 4;
    float* Xw  = sX + wid * 128;
    float* ZPw = (float*)(smem + SM_ZP) + wid * 512;   // [e + side8*8][lane]

    for (int tile = blockIdx.x * NWARPS + wid; tile < ntiles; tile += gridDim.x * NWARPS) {
        const int cell = tile * 16 + c;
        const bool act = (cell < N);

        // each lane owns ONE side of one cell; prefetch flux early
        float rho = 1.0f, p = 1.0f, v = 0.0f;
        float fx0 = 0.0f, fx1 = 0.0f, fx2 = 0.0f;
        if (act) {
            rho = P[cell*6 + side];
            p   = P[cell*6 + 2 + side];
            v   = P[cell*6 + 4 + side];
            fx0 = F[cell*6 + side];
            fx1 = F[cell*6 + 2 + side];
            fx2 = F[cell*6 + 4 + side];
            Xw[c*8 + side]     = fast_log(rho);
            Xw[c*8 + 2 + side] = fast_log(p);
            Xw[c*8 + 4 + side] = v;
        } else {
            Xw[c*8 + side]     = 0.0f;
            Xw[c*8 + 2 + side] = 0.0f;
            Xw[c*8 + 4 + side] = 0.0f;
        }
        if (side == 0) { Xw[c*8 + 6] = 0.0f; Xw[c*8 + 7] = 0.0f; }
        __syncwarp();
        const float aPress = fmaxf(p, __shfl_xor_sync(0xffffffffu, p, 16));

        // per-lane shock invariants
        const float rrho = fast_rcp(rho);
        const float omv2 = 1.0f - v * v;
        const float Wl   = fast_rsqrt(omv2);
        const float hh   = fmaf(2.5f * p, rrho, 1.0f);
        const float hW   = hh * Wl;
        const float rw   = rho * Wl;
        const float a2   = rw * rw;
        const float irW  = rrho * omv2 * Wl;

        // layer1 A-fragments
        uint32_t a1h0, a1l0, a1h1, a1l1;
        {
            float2 f  = *(float2*)&Xw[g*8 + 2*t];
            float2 f8 = *(float2*)&Xw[(g+8)*8 + 2*t];
            split2(f.x,  f.y,  a1h0, a1l0);
            split2(f8.x, f8.y, a1h1, a1l1);
        }
        __syncwarp();

        for (int e = 0; e < NENS; e++) {
            // ---- layer 1: X[16x8] @ W1[8x64] via m16n8k8 ----
            uint32_t A2h[4][4], A2l[4][4];
            const uint4* w1p = sW1p + (e * 8) * 32 + lane;
            #pragma unroll
            for (int nt = 0; nt < 8; nt++) {
                uint4 w = w1p[nt * 32];
                float cH0 = __uint_as_float(w.z), cH1 = __uint_as_float(w.w);
                float cH2 = cH0, cH3 = cH1;
                float cM0=0,cM1=0,cM2=0,cM3=0;
                mma16808(cH0,cH1,cH2,cH3, a1h0,a1h1, w.x);
                mma16808(cM0,cM1,cM2,cM3, a1h0,a1h1, w.y);
                mma16808(cM0,cM1,cM2,cM3, a1l0,a1l1, w.x);
                float r0, r1, r2, r3;
                quad_r(cH0+cM0, cH1+cM1, cH2+cM2, cH3+cM3, r0, r1, r2, r3);
                int kt = nt >> 1, hhp = (nt & 1) * 2;
                split2(r0, r1, A2h[kt][hhp],     A2l[kt][hhp]);
                split2(r2, r3, A2h[kt][hhp + 1], A2l[kt][hhp + 1]);
            }

            // ---- layers 2+3: 3 independent chains (len 4) + factored z ----
            float zp0 = 0.0f, zp1 = 0.0f;
            const uint4* w2p = sW2p + (e * 8) * 4 * 32 + lane;
            #pragma unroll 2
            for (int nt = 0; nt < 8; nt++) {
                float4 bw = sBW[(e*8 + nt)*4 + t];
                float cH0=bw.x, cH1=bw.y, cH2=bw.x, cH3=bw.y;
                float cM0=0,cM1=0,cM2=0,cM3=0;
                float cL0=0,cL1=0,cL2=0,cL3=0;
                const uint4* wrow = w2p + nt * (4*32);
                #pragma unroll
                for (int kt = 0; kt < 4; kt++) {
                    uint4 w = wrow[kt * 32];
                    mma16816(cH0,cH1,cH2,cH3, A2h[kt][0],A2h[kt][1],A2h[kt][2],A2h[kt][3], w.x,w.y);
                    mma16816(cM0,cM1,cM2,cM3, A2h[kt][0],A2h[kt][1],A2h[kt][2],A2h[kt][3], w.z,w.w);
                    mma16816(cL0,cL1,cL2,cL3, A2l[kt][0],A2l[kt][1],A2l[kt][2],A2l[kt][3], w.x,w.y);
                }
                // factored z: zp0 += q*pb*(w3z*e1p + w3w*e0p); zp1 += q*pa*(...)
                float e0p = fast_ex2(cH0 + cM0 + cL0) + 1.0f;
                float e1p = fast_ex2(cH1 + cM1 + cL1) + 1.0f;
                float e2p = fast_ex2(cH2 + cM2 + cL2) + 1.0f;
                float e3p = fast_ex2(cH3 + cM3 + cL3) + 1.0f;
                float pa = e0p * e1p, pb = e2p * e3p;
                float q  = fast_rcp(pa * pb);
                float u0 = bw.z * e1p;  u0 = fmaf(bw.w, e0p, u0);
                float u1 = bw.z * e3p;  u1 = fmaf(bw.w, e2p, u1);
                zp0 = fmaf(u0, q * pb, zp0);
                zp1 = fmaf(u1, q * pa, zp1);
            }
            // stash partials; ALL reductions + shocks deferred past the loop
            ZPw[e*32 + lane]       = zp0;
            ZPw[256 + e*32 + lane] = zp1;
        }
        __syncwarp();

        // ============ deferred tail: 8 reductions + 8 shocks, full ILP =====
        float zA[NENS], zB[NENS];
        #pragma unroll
        for (int e = 0; e < NENS; e++) {
            zA[e] = ZPw[e*32 + lane];
            zB[e] = ZPw[256 + e*32 + lane];
        }
        #pragma unroll
        for (int e = 0; e < NENS; e++) {
            zA[e] += __shfl_xor_sync(0xffffffffu, zA[e], 1);
            zB[e] += __shfl_xor_sync(0xffffffffu, zB[e], 1);
        }
        #pragma unroll
        for (int e = 0; e < NENS; e++) {
            zA[e] += __shfl_xor_sync(0xffffffffu, zA[e], 2);
            zB[e] += __shfl_xor_sync(0xffffffffu, zB[e], 2);
        }
        const int src = (c & 7) * 4;
        float pc[NENS];
        #pragma unroll
        for (int e = 0; e < NENS; e++) {
            float za = __shfl_sync(0xffffffffu, zA[e], src);
            float zb = __shfl_sync(0xffffffffu, zB[e], src);
            float z  = ((c < 8) ? za : zb) + sB3[e];   // log2e-scaled
            pc[e] = aPress * fmaf(2.0f, fast_ex2(z), 1.0f);
        }
        float vs[NENS];
        #pragma unroll
        for (int e = 0; e < NENS; e++)
            vs[e] = vstar_light(pc[e], p, v, sgn, rrho, omv2, hh, hW, a2, irW);

        float bestdiff = 3.4e38f, bestP = 0.0f;
        #pragma unroll
        for (int e = 0; e < NENS; e++) {
            float vsO = __shfl_xor_sync(0xffffffffu, vs[e], 16);
            float d = fabsf(vs[e] - vsO);     // symmetric: both lanes agree
            if (d < bestdiff) { bestdiff = d; bestP = pc[e]; }
        }

        // final shock recompute, parallel over sides; exchange via shfl
        float rhoC, hC, vstar, vsh;
        get_vel_shock(bestP, rho, p, v, sgn, rhoC, hC, vstar, vsh);
        float vstarO = __shfl_xor_sync(0xffffffffu, vstar, 16);
        float vshO   = __shfl_xor_sync(0xffffffffu, vsh,   16);
        float rhoCO  = __shfl_xor_sync(0xffffffffu, rhoC,  16);
        float hCO    = __shfl_xor_sync(0xffffffffu, hC,    16);
        float fR0    = __shfl_xor_sync(0xffffffffu, fx0,   16);
        float fR1    = __shfl_xor_sync(0xffffffffu, fx1,   16);
        float fR2    = __shfl_xor_sync(0xffffffffu, fx2,   16);

        if (side == 0 && act) {
            float lam = 0.5f * (vstarO + vstar);
            float WC  = fast_rsqrt(1.0f - lam * lam);
            float densCL = WC * rhoC, densCR = WC * rhoCO;

            float f0 = 0.0f, f1 = 0.0f, f2 = 0.0f;
            if (vsh >= 0.0f) { f0 = fx0; f1 = fx1; f2 = fx2; }
            if (vsh < 0.0f && lam > 0.0f) {
                f0 = densCL * lam;
                f1 = densCL * (WC * hC - 1.0f) * lam;
                f2 = (WC * WC * rhoC * hC * lam) * lam + bestP;
            }
            if (lam <= 0.0f && vshO > 0.0f) {
                f0 = densCR * lam;
                f1 = densCR * (WC * hCO - 1.0f) * lam;
                f2 = (WC * WC * rhoCO * hCO * lam) * lam + bestP;
            }
            if (vshO <= 0.0f) { f0 = fR0; f1 = fR1; f2 = fR2; }
            out[cell*3+0] = f0; out[cell*3+1] = f1; out[cell*3+2] = f2;
        }
    }
}

extern "C" void kernel_launch(void* const* d_in, const int* in_sizes, int n_in,
                              void* d_out, int out_size)
{
    const float* P  = (const float*)d_in[0];
    const float* F  = (const float*)d_in[2];
    const float* W1 = (const float*)d_in[5];
    const float* b1 = (const float*)d_in[6];
    const float* W2 = (const float*)d_in[7];
    const float* b2 = (const float*)d_in[8];
    const float* W3 = (const float*)d_in[9];
    const float* b3 = (const float*)d_in[10];
    float* out = (float*)d_out;
    const int N = in_sizes[0] / 6;

    const int nprep = NENS*8*4*32 + NENS*8*32 + NENS*8*4 + NENS;
    prep_kernel<<<(nprep + 255) / 256, 256>>>(W1, W2, b1, b2, W3, b3);

    cudaFuncSetAttribute(solver_mma,
                         cudaFuncAttributeMaxDynamicSharedMemorySize, SMEM_BYTES);
    solver_mma<<<148, NTHREADS, SMEM_BYTES>>>(P, F, out, N);
}